// round 3
// baseline (speedup 1.0000x reference)
#include <cuda_runtime.h>
#include <cuda_bf16.h>
#include <math.h>

// ---------------- problem constants ----------------
#define T_DIM   2048
#define HID     5120
#define QLR     1536
#define KVLR    512
#define NOPE    128
#define ROPE_D  64
#define VDIM    128
#define H_HEADS 32
#define QKD     192            // NOPE + ROPE
#define DQK     576            // KVLR + ROPE  (q_input / k_input dim)
#define ATTN_SCALE 0.07216878364870323f   // 192^-0.5
#define RMS_EPS 1e-6f

// ---------------- scratch (static device globals; allocation-free) ----------
__device__ float g_qa    [T_DIM * QLR];                 // hidden @ w_q_a
__device__ float g_qan   [T_DIM * QLR];                 // rmsnorm(g_qa)
__device__ float g_qproj [T_DIM * H_HEADS * QKD];       // q (pre-split)
__device__ float g_latent[T_DIM * DQK];                 // hidden @ w_kv_a
__device__ float g_kin   [T_DIM * DQK];                 // [v_input | roped k_pe]
__device__ float g_cs    [T_DIM * ROPE_D];              // per-t cos[32], sin[32]
__device__ float g_qin   [37748736];                    // [H][T][576]
__device__ float g_scores[134217728];                   // [H][T][T]
__device__ float g_ctx   [33554432];                    // [H][T][512]
__device__ float g_attn  [T_DIM * H_HEADS * VDIM];      // [T][H*128]

// ---------------- generic fp32 tiled GEMM ----------------------------------
// C[M,N] = alpha * A[M,K] (@ B or @ B^T), row-major, optional batching via
// blockIdx.z with element strides sA/sB/sC.
// CAUSAL==1: (scores, requires TRANSB) skip blocks strictly above diagonal.
// CAUSAL==2: (ctx) clamp K to the causal tile limit m0+128.
// Assumes: M % 128 == 0, K % 8 == 0, lda/ldb/ldc % 4 == 0, pointers 16B-aligned.
template <bool TRANSB, int CAUSAL>
__global__ __launch_bounds__(256, 2)
void sgemm(const float* __restrict__ A, const float* __restrict__ B,
           float* __restrict__ C,
           int M, int N, int K, int lda, int ldb, int ldc,
           long long sA, long long sB, long long sC, float alpha)
{
    const int m0 = blockIdx.y * 128;
    const int n0 = blockIdx.x * 128;
    if (CAUSAL == 1 && n0 > m0 + 127) return;   // fully masked tile

    A += (long long)blockIdx.z * sA;
    B += (long long)blockIdx.z * sB;
    C += (long long)blockIdx.z * sC;

    const int Keff = (CAUSAL == 2) ? min(K, m0 + 128) : K;

    __shared__ float As[8][128];
    __shared__ float Bs[8][128];

    const int tid  = threadIdx.x;
    const int trow = tid >> 4;      // 0..15
    const int tcol = tid & 15;      // 0..15

    float acc[8][8];
#pragma unroll
    for (int i = 0; i < 8; i++)
#pragma unroll
        for (int j = 0; j < 8; j++) acc[i][j] = 0.f;

    const int arow = tid >> 1;          // 0..127
    const int acol = (tid & 1) * 4;     // 0 or 4

    for (int k0 = 0; k0 < Keff; k0 += 8) {
        // ---- A tile: 128 x 8, stored transposed As[k][m]
        {
            float4 a4 = *(const float4*)(A + (long long)(m0 + arow) * lda + k0 + acol);
            As[acol + 0][arow] = a4.x;
            As[acol + 1][arow] = a4.y;
            As[acol + 2][arow] = a4.z;
            As[acol + 3][arow] = a4.w;
        }
        // ---- B tile
        if (TRANSB) {
            const int brow = tid >> 1;          // n 0..127
            const int bcol = (tid & 1) * 4;     // k
            float4 b4 = make_float4(0.f, 0.f, 0.f, 0.f);
            if (n0 + brow < N)
                b4 = *(const float4*)(B + (long long)(n0 + brow) * ldb + k0 + bcol);
            Bs[bcol + 0][brow] = b4.x;
            Bs[bcol + 1][brow] = b4.y;
            Bs[bcol + 2][brow] = b4.z;
            Bs[bcol + 3][brow] = b4.w;
        } else {
            const int bk = tid >> 5;            // 0..7
            const int bn = (tid & 31) * 4;      // 0..124
            const float* bp = B + (long long)(k0 + bk) * ldb + n0 + bn;
            float4 b4;
            if (n0 + bn + 3 < N) {
                b4 = *(const float4*)bp;
            } else {
                b4.x = (n0 + bn + 0 < N) ? bp[0] : 0.f;
                b4.y = (n0 + bn + 1 < N) ? bp[1] : 0.f;
                b4.z = (n0 + bn + 2 < N) ? bp[2] : 0.f;
                b4.w = (n0 + bn + 3 < N) ? bp[3] : 0.f;
            }
            *(float4*)&Bs[bk][bn] = b4;
        }
        __syncthreads();

#pragma unroll
        for (int kk = 0; kk < 8; kk++) {
            float a[8], b[8];
            *(float4*)&a[0] = *(const float4*)&As[kk][trow * 8];
            *(float4*)&a[4] = *(const float4*)&As[kk][trow * 8 + 4];
            *(float4*)&b[0] = *(const float4*)&Bs[kk][tcol * 8];
            *(float4*)&b[4] = *(const float4*)&Bs[kk][tcol * 8 + 4];
#pragma unroll
            for (int i = 0; i < 8; i++)
#pragma unroll
                for (int j = 0; j < 8; j++)
                    acc[i][j] += a[i] * b[j];
        }
        __syncthreads();
    }

    // ---- epilogue
#pragma unroll
    for (int i = 0; i < 8; i++) {
        const int m = m0 + trow * 8 + i;
        float* cp = C + (long long)m * ldc + n0 + tcol * 8;
        if (n0 + tcol * 8 + 7 < N) {
            float4 c0 = make_float4(acc[i][0] * alpha, acc[i][1] * alpha,
                                    acc[i][2] * alpha, acc[i][3] * alpha);
            float4 c1 = make_float4(acc[i][4] * alpha, acc[i][5] * alpha,
                                    acc[i][6] * alpha, acc[i][7] * alpha);
            *(float4*)cp       = c0;
            *((float4*)cp + 1) = c1;
        } else {
#pragma unroll
            for (int j = 0; j < 8; j++)
                if (n0 + tcol * 8 + j < N) cp[j] = acc[i][j] * alpha;
        }
    }
}

// ---------------- RMSNorm (one block per row) -------------------------------
__global__ void rmsnorm_kernel(const float* __restrict__ x,
                               const float* __restrict__ w,
                               float* __restrict__ y, int D)
{
    const int row = blockIdx.x;
    const float* xr = x + (long long)row * D;
    float* yr       = y + (long long)row * D;

    float ss = 0.f;
    for (int i = threadIdx.x; i < D; i += 256) { float v = xr[i]; ss += v * v; }
    __shared__ float red[256];
    red[threadIdx.x] = ss;
    __syncthreads();
    for (int s = 128; s > 0; s >>= 1) {
        if (threadIdx.x < s) red[threadIdx.x] += red[threadIdx.x + s];
        __syncthreads();
    }
    const float r = rsqrtf(red[0] / (float)D + RMS_EPS);
    for (int i = threadIdx.x; i < D; i += 256) yr[i] = xr[i] * r * w[i];
}

// ---------------- build k_input: rmsnorm(latent[:512]) + rope(k_pe) ---------
// positions may arrive as int32 or int64 depending on harness dtype handling.
// Sniff on-device: int64 little-endian arange has p32[1]==0 (high word of
// element 0); int32 arange has p32[1]==1. Deterministic for the given inputs.
__global__ void build_k_kernel(const float* __restrict__ latent,
                               const float* __restrict__ w,
                               const int* __restrict__ pos32,
                               float* __restrict__ kin,
                               float* __restrict__ cs)
{
    const int t = blockIdx.x;
    const float* lr = latent + (long long)t * DQK;
    float* kr       = kin    + (long long)t * DQK;

    float ss = 0.f;
    for (int i = threadIdx.x; i < KVLR; i += 256) { float v = lr[i]; ss += v * v; }
    __shared__ float red[256];
    red[threadIdx.x] = ss;
    __syncthreads();
    for (int s = 128; s > 0; s >>= 1) {
        if (threadIdx.x < s) red[threadIdx.x] += red[threadIdx.x + s];
        __syncthreads();
    }
    const float r = rsqrtf(red[0] / (float)KVLR + RMS_EPS);
    for (int i = threadIdx.x; i < KVLR; i += 256) kr[i] = lr[i] * r * w[i];

    if (threadIdx.x < 32) {
        const int j = threadIdx.x;
        const bool is64 = (pos32[1] == 0);   // int64 layout: high word of pos[0]
        const long long p = is64 ? ((const long long*)pos32)[t]
                                 : (long long)pos32[t];
        const double inv = pow(10000.0, -(double)(2 * j) / (double)ROPE_D);
        const double ang = (double)p * inv;
        const float c = (float)cos(ang);
        const float s = (float)sin(ang);
        cs[t * ROPE_D + j]      = c;
        cs[t * ROPE_D + 32 + j] = s;
        const float x1 = lr[KVLR + 2 * j];
        const float x2 = lr[KVLR + 2 * j + 1];
        kr[KVLR + 2 * j]     = x1 * c - x2 * s;
        kr[KVLR + 2 * j + 1] = x2 * c + x1 * s;
    }
}

// ---------------- rope q_pe into q_input[.., 512:576] -----------------------
__global__ void rope_q_kernel(const float* __restrict__ q,
                              const float* __restrict__ cs,
                              float* __restrict__ qin)
{
    const int t = blockIdx.x;
    const int h = blockIdx.y * blockDim.y + threadIdx.y;
    const int j = threadIdx.x;   // 0..31

    const float c = cs[t * ROPE_D + j];
    const float s = cs[t * ROPE_D + 32 + j];
    const float* qr = q + (long long)t * (H_HEADS * QKD) + h * QKD + NOPE;
    const float x1 = qr[2 * j];
    const float x2 = qr[2 * j + 1];
    float* o = qin + ((long long)h * T_DIM + t) * DQK + KVLR;
    o[2 * j]     = x1 * c - x2 * s;
    o[2 * j + 1] = x2 * c + x1 * s;
}

// ---------------- causal softmax (one block per (t,h) row) ------------------
__global__ void softmax_kernel(float* __restrict__ scores)
{
    const int t = blockIdx.x;
    const int h = blockIdx.y;
    float* row = scores + ((long long)h * T_DIM + t) * T_DIM;
    const int len = t + 1;

    __shared__ float red[256];

    float mx = -1e30f;
    for (int i = threadIdx.x; i < len; i += 256) mx = fmaxf(mx, row[i]);
    red[threadIdx.x] = mx;
    __syncthreads();
    for (int s = 128; s > 0; s >>= 1) {
        if (threadIdx.x < s) red[threadIdx.x] = fmaxf(red[threadIdx.x], red[threadIdx.x + s]);
        __syncthreads();
    }
    mx = red[0];
    __syncthreads();

    float sum = 0.f;
    for (int i = threadIdx.x; i < len; i += 256) sum += expf(row[i] - mx);
    red[threadIdx.x] = sum;
    __syncthreads();
    for (int s = 128; s > 0; s >>= 1) {
        if (threadIdx.x < s) red[threadIdx.x] += red[threadIdx.x + s];
        __syncthreads();
    }
    const float inv = 1.f / red[0];

    for (int i = threadIdx.x; i < len; i += 256) row[i] = expf(row[i] - mx) * inv;

    // zero-fill only up to the 128-aligned tile boundary — ctx GEMM clamps K there
    const int zend = min(T_DIM, ((t >> 7) + 1) << 7);
    for (int i = len + threadIdx.x; i < zend; i += 256) row[i] = 0.f;
}

// ---------------- launch ----------------------------------------------------
extern "C" void kernel_launch(void* const* d_in, const int* in_sizes, int n_in,
                              void* d_out, int out_size)
{
    const float*     hidden     = (const float*)d_in[0];
    const int*       positions  = (const int*)d_in[1];   // int32 or int64 bits — sniffed on device
    const float*     w_q_a      = (const float*)d_in[2];
    const float*     q_a_ln_w   = (const float*)d_in[3];
    const float*     w_q_b      = (const float*)d_in[4];
    const float*     w_kv_a     = (const float*)d_in[5];
    const float*     kv_a_ln_w  = (const float*)d_in[6];
    const float*     w_kc       = (const float*)d_in[7];
    const float*     w_vc       = (const float*)d_in[8];
    const float*     w_o        = (const float*)d_in[9];
    float*           out        = (float*)d_out;

    float *qa, *qan, *qproj, *latent, *kin, *cs, *qin, *scores, *ctx, *attn;
    cudaGetSymbolAddress((void**)&qa,     g_qa);
    cudaGetSymbolAddress((void**)&qan,    g_qan);
    cudaGetSymbolAddress((void**)&qproj,  g_qproj);
    cudaGetSymbolAddress((void**)&latent, g_latent);
    cudaGetSymbolAddress((void**)&kin,    g_kin);
    cudaGetSymbolAddress((void**)&cs,     g_cs);
    cudaGetSymbolAddress((void**)&qin,    g_qin);
    cudaGetSymbolAddress((void**)&scores, g_scores);
    cudaGetSymbolAddress((void**)&ctx,    g_ctx);
    cudaGetSymbolAddress((void**)&attn,   g_attn);

    // 1. q_a = hidden @ w_q_a                        [2048,5120]x[5120,1536]
    sgemm<false, 0><<<dim3(QLR / 128, T_DIM / 128, 1), 256>>>(
        hidden, w_q_a, qa, T_DIM, QLR, HID, HID, QLR, QLR, 0, 0, 0, 1.f);

    // 2. q_a_norm = rmsnorm(q_a)
    rmsnorm_kernel<<<T_DIM, 256>>>(qa, q_a_ln_w, qan, QLR);

    // 3. q = q_a_norm @ w_q_b                        [2048,1536]x[1536,6144]
    sgemm<false, 0><<<dim3(48, T_DIM / 128, 1), 256>>>(
        qan, w_q_b, qproj, T_DIM, H_HEADS * QKD, QLR,
        QLR, H_HEADS * QKD, H_HEADS * QKD, 0, 0, 0, 1.f);

    // 4. latent = hidden @ w_kv_a                    [2048,5120]x[5120,576]
    sgemm<false, 0><<<dim3((DQK + 127) / 128, T_DIM / 128, 1), 256>>>(
        hidden, w_kv_a, latent, T_DIM, DQK, HID, HID, DQK, DQK, 0, 0, 0, 1.f);

    // 5. k_input = [rmsnorm(latent[:,:512]) | rope(latent[:,512:])]; cos/sin table
    build_k_kernel<<<T_DIM, 256>>>(latent, kv_a_ln_w, positions, kin, cs);

    // 6. q_input[h][:, :512] = q_nope_h @ w_kc[h]    batched [2048,128]x[128,512]
    sgemm<false, 0><<<dim3(KVLR / 128, T_DIM / 128, H_HEADS), 256>>>(
        qproj, w_kc, qin, T_DIM, KVLR, NOPE,
        H_HEADS * QKD, KVLR, DQK,
        (long long)QKD, (long long)NOPE * KVLR, (long long)T_DIM * DQK, 1.f);

    // 7. q_input[h][:, 512:576] = rope(q_pe)
    rope_q_kernel<<<dim3(T_DIM, H_HEADS / 8), dim3(32, 8)>>>(qproj, cs, qin);

    // 8. scores[h] = SCALE * q_input[h] @ k_input^T  (causal block-skip)
    sgemm<true, 1><<<dim3(T_DIM / 128, T_DIM / 128, H_HEADS), 256>>>(
        qin, kin, scores, T_DIM, T_DIM, DQK, DQK, DQK, T_DIM,
        (long long)T_DIM * DQK, 0, (long long)T_DIM * T_DIM, ATTN_SCALE);

    // 9. causal softmax (zero-fills up to tile boundary)
    softmax_kernel<<<dim3(T_DIM, H_HEADS), 256>>>(scores);

    // 10. ctx[h] = probs[h] @ v_input                (K clamped causally)
    sgemm<false, 2><<<dim3(KVLR / 128, T_DIM / 128, H_HEADS), 256>>>(
        scores, kin, ctx, T_DIM, KVLR, T_DIM, T_DIM, DQK, KVLR,
        (long long)T_DIM * T_DIM, 0, (long long)T_DIM * KVLR, 1.f);

    // 11. attn[:, h*128:(h+1)*128] = ctx[h] @ w_vc[h]  batched [2048,512]x[512,128]
    sgemm<false, 0><<<dim3(1, T_DIM / 128, H_HEADS), 256>>>(
        ctx, w_vc, attn, T_DIM, VDIM, KVLR, KVLR, VDIM, H_HEADS * VDIM,
        (long long)T_DIM * KVLR, (long long)KVLR * VDIM, (long long)VDIM, 1.f);

    // 12. out = attn @ w_o                           [2048,4096]x[4096,5120]
    sgemm<false, 0><<<dim3(HID / 128, T_DIM / 128, 1), 256>>>(
        attn, w_o, out, T_DIM, HID, H_HEADS * VDIM,
        H_HEADS * VDIM, HID, HID, 0, 0, 0, 1.f);
}

// round 4
// speedup vs baseline: 1.9791x; 1.9791x over previous
#include <cuda_runtime.h>
#include <cuda_bf16.h>
#include <math.h>
#include <stdint.h>

// ---------------- problem constants ----------------
#define T_DIM   2048
#define HID     5120
#define QLR     1536
#define KVLR    512
#define NOPE    128
#define ROPE_D  64
#define VDIM    128
#define H_HEADS 32
#define QKD     192            // NOPE + ROPE
#define DQK     576            // KVLR + ROPE
#define ATTN_SCALE 0.07216878364870323f   // 192^-0.5
#define RMS_EPS 1e-6f

// ---------------- scratch (static device globals; allocation-free) ----------
__device__ float g_qa    [T_DIM * QLR];
__device__ float g_qan   [T_DIM * QLR];
__device__ float g_qproj [T_DIM * H_HEADS * QKD];
__device__ float g_latent[T_DIM * DQK];
__device__ float g_kin   [T_DIM * DQK];
__device__ float g_cs    [T_DIM * ROPE_D];
__device__ float g_qin   [37748736];                    // [H][T][576]
__device__ float g_scores[134217728];                   // [H][T][T]
__device__ float g_ctx   [33554432];                    // [H][T][512]
__device__ float g_attn  [T_DIM * H_HEADS * VDIM];

// ---------------- bf16x2-split tensor-core GEMM ------------------------------
// C[M,N] = alpha * A[M,K] (@B or @B^T), fp32 in/out. Internally each fp32
// operand is split x = hi + lo (bf16 each); D += Ahi*Bhi + Ahi*Blo + Alo*Bhi
// with fp32 accumulate -> per-element error ~2^-17 (way under 1e-3 gate).
// Block tile 128x128x16, 256 threads = 8 warps (2x4), warp tile 64x32,
// mma.sync.m16n8k16. Double-buffered smem.
// CAUSAL==1: skip tiles strictly above diagonal (scores, TRANSB).
// CAUSAL==2: clamp K at m0+128 (ctx).
// Requires: M%128==0, K%16==0, Keff%16==0, N even, lda/ldb%4==0, 16B-aligned ptrs.

typedef uint32_t Tile9[128][9];   // packed bf16 pairs: [row][k_pair], pad to 9

__device__ __forceinline__ void splitpack(float x, float y,
                                          uint32_t& hi, uint32_t& lo)
{
    __nv_bfloat16 hx = __float2bfloat16(x);
    __nv_bfloat16 hy = __float2bfloat16(y);
    __nv_bfloat16 lx = __float2bfloat16(x - __bfloat162float(hx));
    __nv_bfloat16 ly = __float2bfloat16(y - __bfloat162float(hy));
    hi = (uint32_t)__bfloat16_as_ushort(hx) | ((uint32_t)__bfloat16_as_ushort(hy) << 16);
    lo = (uint32_t)__bfloat16_as_ushort(lx) | ((uint32_t)__bfloat16_as_ushort(ly) << 16);
}

#define MMA16816(c, a, b)                                                      \
    asm volatile("mma.sync.aligned.m16n8k16.row.col.f32.bf16.bf16.f32 "        \
                 "{%0,%1,%2,%3},{%4,%5,%6,%7},{%8,%9},{%0,%1,%2,%3};"          \
                 : "+f"((c)[0]), "+f"((c)[1]), "+f"((c)[2]), "+f"((c)[3])      \
                 : "r"((a)[0]), "r"((a)[1]), "r"((a)[2]), "r"((a)[3]),         \
                   "r"((b)[0]), "r"((b)[1]))

template <bool TRANSB, int CAUSAL>
__global__ __launch_bounds__(256, 2)
void hgemm(const float* __restrict__ A, const float* __restrict__ B,
           float* __restrict__ C,
           int M, int N, int K, int lda, int ldb, int ldc,
           long long sA, long long sB, long long sC, float alpha)
{
    const int m0 = blockIdx.y * 128;
    const int n0 = blockIdx.x * 128;
    if (CAUSAL == 1 && n0 > m0 + 127) return;

    A += (long long)blockIdx.z * sA;
    B += (long long)blockIdx.z * sB;
    C += (long long)blockIdx.z * sC;

    const int Keff = (CAUSAL == 2) ? min(K, m0 + 128) : K;

    __shared__ uint32_t Ah[2][128][9], Al[2][128][9];
    __shared__ uint32_t Bh[2][128][9], Bl[2][128][9];

    const int tid  = threadIdx.x;
    const int lane = tid & 31;
    const int warp = tid >> 5;
    const int gid  = lane >> 2;     // 0..7
    const int tig  = lane & 3;      // 0..3
    const int warpM = (warp & 1) * 64;
    const int warpN = (warp >> 1) * 32;

    float acc[4][4][4];
#pragma unroll
    for (int i = 0; i < 4; i++)
#pragma unroll
        for (int j = 0; j < 4; j++)
#pragma unroll
            for (int c = 0; c < 4; c++) acc[i][j][c] = 0.f;

    // ---------------- tile loaders (global fp32 -> split bf16 smem) ----------
    auto loadTile = [&](int k0, int buf) {
        // A: 128 rows x 16 k, float4 per thread x2
#pragma unroll
        for (int u = 0; u < 2; u++) {
            int idx = tid + u * 256;
            int row = idx >> 2;
            int c4  = idx & 3;
            float4 f = *(const float4*)(A + (long long)(m0 + row) * lda + k0 + c4 * 4);
            uint32_t h0, l0, h1, l1;
            splitpack(f.x, f.y, h0, l0);
            splitpack(f.z, f.w, h1, l1);
            Ah[buf][row][c4 * 2]     = h0;  Al[buf][row][c4 * 2]     = l0;
            Ah[buf][row][c4 * 2 + 1] = h1;  Al[buf][row][c4 * 2 + 1] = l1;
        }
        if (TRANSB) {
            // B[n][k] -> Bs[n][kpair]; same pattern as A
#pragma unroll
            for (int u = 0; u < 2; u++) {
                int idx = tid + u * 256;
                int n  = idx >> 2;
                int c4 = idx & 3;
                float4 f = make_float4(0.f, 0.f, 0.f, 0.f);
                if (n0 + n < N)
                    f = *(const float4*)(B + (long long)(n0 + n) * ldb + k0 + c4 * 4);
                uint32_t h0, l0, h1, l1;
                splitpack(f.x, f.y, h0, l0);
                splitpack(f.z, f.w, h1, l1);
                Bh[buf][n][c4 * 2]     = h0;  Bl[buf][n][c4 * 2]     = l0;
                Bh[buf][n][c4 * 2 + 1] = h1;  Bl[buf][n][c4 * 2 + 1] = l1;
            }
        } else {
            // B[k][n]: pack pairs across two k-rows. 8 kpairs x 32 n4-groups.
            int kp = tid >> 5;           // 0..7
            int n4 = (tid & 31) * 4;     // 0..124
            const float* p0 = B + (long long)(k0 + 2 * kp) * ldb + n0 + n4;
            const float* p1 = p0 + ldb;
            float4 f0 = make_float4(0.f, 0.f, 0.f, 0.f);
            float4 f1 = make_float4(0.f, 0.f, 0.f, 0.f);
            if (n0 + n4 + 3 < N) {
                f0 = *(const float4*)p0;
                f1 = *(const float4*)p1;
            } else {
                float* e0 = (float*)&f0; float* e1 = (float*)&f1;
#pragma unroll
                for (int c = 0; c < 4; c++)
                    if (n0 + n4 + c < N) { e0[c] = p0[c]; e1[c] = p1[c]; }
            }
            const float* e0 = (const float*)&f0;
            const float* e1 = (const float*)&f1;
#pragma unroll
            for (int c = 0; c < 4; c++) {
                uint32_t h, l;
                splitpack(e0[c], e1[c], h, l);
                Bh[buf][n4 + c][kp] = h;
                Bl[buf][n4 + c][kp] = l;
            }
        }
    };

    loadTile(0, 0);
    __syncthreads();

    const int nk = Keff / 16;
    int buf = 0;
    for (int it = 0; it < nk; it++) {
        if (it + 1 < nk) loadTile((it + 1) * 16, buf ^ 1);

        // ---------------- compute on smem[buf] -------------------------------
        uint32_t af[4][4], bh4[4][2], bl4[4][2];
#pragma unroll
        for (int i = 0; i < 4; i++) {
            int m = warpM + i * 16 + gid;
            af[i][0] = Ah[buf][m][tig];
            af[i][1] = Ah[buf][m + 8][tig];
            af[i][2] = Ah[buf][m][tig + 4];
            af[i][3] = Ah[buf][m + 8][tig + 4];
        }
#pragma unroll
        for (int j = 0; j < 4; j++) {
            int n = warpN + j * 8 + gid;
            bh4[j][0] = Bh[buf][n][tig];
            bh4[j][1] = Bh[buf][n][tig + 4];
            bl4[j][0] = Bl[buf][n][tig];
            bl4[j][1] = Bl[buf][n][tig + 4];
        }
#pragma unroll
        for (int i = 0; i < 4; i++)
#pragma unroll
            for (int j = 0; j < 4; j++) {
                MMA16816(acc[i][j], af[i], bh4[j]);   // hi*hi
                MMA16816(acc[i][j], af[i], bl4[j]);   // hi*lo
            }
#pragma unroll
        for (int i = 0; i < 4; i++) {
            int m = warpM + i * 16 + gid;
            af[i][0] = Al[buf][m][tig];
            af[i][1] = Al[buf][m + 8][tig];
            af[i][2] = Al[buf][m][tig + 4];
            af[i][3] = Al[buf][m + 8][tig + 4];
        }
#pragma unroll
        for (int i = 0; i < 4; i++)
#pragma unroll
            for (int j = 0; j < 4; j++)
                MMA16816(acc[i][j], af[i], bh4[j]);   // lo*hi

        __syncthreads();
        buf ^= 1;
    }

    // ---------------- epilogue ------------------------------------------------
#pragma unroll
    for (int i = 0; i < 4; i++) {
#pragma unroll
        for (int j = 0; j < 4; j++) {
            int r0 = m0 + warpM + i * 16 + gid;
            int cn = n0 + warpN + j * 8 + 2 * tig;
            if (cn < N) {   // N even -> pair-safe
                float2 v0 = make_float2(acc[i][j][0] * alpha, acc[i][j][1] * alpha);
                float2 v1 = make_float2(acc[i][j][2] * alpha, acc[i][j][3] * alpha);
                *(float2*)(C + (long long)r0 * ldc + cn)       = v0;
                *(float2*)(C + (long long)(r0 + 8) * ldc + cn) = v1;
            }
        }
    }
}

// ---------------- RMSNorm (one block per row) -------------------------------
__global__ void rmsnorm_kernel(const float* __restrict__ x,
                               const float* __restrict__ w,
                               float* __restrict__ y, int D)
{
    const int row = blockIdx.x;
    const float* xr = x + (long long)row * D;
    float* yr       = y + (long long)row * D;

    float ss = 0.f;
    for (int i = threadIdx.x; i < D; i += 256) { float v = xr[i]; ss += v * v; }
    __shared__ float red[256];
    red[threadIdx.x] = ss;
    __syncthreads();
    for (int s = 128; s > 0; s >>= 1) {
        if (threadIdx.x < s) red[threadIdx.x] += red[threadIdx.x + s];
        __syncthreads();
    }
    const float r = rsqrtf(red[0] / (float)D + RMS_EPS);
    for (int i = threadIdx.x; i < D; i += 256) yr[i] = xr[i] * r * w[i];
}

// ---------------- build k_input + cos/sin table -----------------------------
__global__ void build_k_kernel(const float* __restrict__ latent,
                               const float* __restrict__ w,
                               const int* __restrict__ pos32,
                               float* __restrict__ kin,
                               float* __restrict__ cs)
{
    const int t = blockIdx.x;
    const float* lr = latent + (long long)t * DQK;
    float* kr       = kin    + (long long)t * DQK;

    float ss = 0.f;
    for (int i = threadIdx.x; i < KVLR; i += 256) { float v = lr[i]; ss += v * v; }
    __shared__ float red[256];
    red[threadIdx.x] = ss;
    __syncthreads();
    for (int s = 128; s > 0; s >>= 1) {
        if (threadIdx.x < s) red[threadIdx.x] += red[threadIdx.x + s];
        __syncthreads();
    }
    const float r = rsqrtf(red[0] / (float)KVLR + RMS_EPS);
    for (int i = threadIdx.x; i < KVLR; i += 256) kr[i] = lr[i] * r * w[i];

    if (threadIdx.x < 32) {
        const int j = threadIdx.x;
        const bool is64 = (pos32[1] == 0);   // int64 LE: high word of pos[0]
        const long long p = is64 ? ((const long long*)pos32)[t]
                                 : (long long)pos32[t];
        const double inv = pow(10000.0, -(double)(2 * j) / (double)ROPE_D);
        const double ang = (double)p * inv;
        const float c = (float)cos(ang);
        const float s = (float)sin(ang);
        cs[t * ROPE_D + j]      = c;
        cs[t * ROPE_D + 32 + j] = s;
        const float x1 = lr[KVLR + 2 * j];
        const float x2 = lr[KVLR + 2 * j + 1];
        kr[KVLR + 2 * j]     = x1 * c - x2 * s;
        kr[KVLR + 2 * j + 1] = x2 * c + x1 * s;
    }
}

// ---------------- rope q_pe into q_input[.., 512:576] -----------------------
__global__ void rope_q_kernel(const float* __restrict__ q,
                              const float* __restrict__ cs,
                              float* __restrict__ qin)
{
    const int t = blockIdx.x;
    const int h = blockIdx.y * blockDim.y + threadIdx.y;
    const int j = threadIdx.x;   // 0..31

    const float c = cs[t * ROPE_D + j];
    const float s = cs[t * ROPE_D + 32 + j];
    const float* qr = q + (long long)t * (H_HEADS * QKD) + h * QKD + NOPE;
    const float x1 = qr[2 * j];
    const float x2 = qr[2 * j + 1];
    float* o = qin + ((long long)h * T_DIM + t) * DQK + KVLR;
    o[2 * j]     = x1 * c - x2 * s;
    o[2 * j + 1] = x2 * c + x1 * s;
}

// ---------------- causal softmax ---------------------------------------------
__global__ void softmax_kernel(float* __restrict__ scores)
{
    const int t = blockIdx.x;
    const int h = blockIdx.y;
    float* row = scores + ((long long)h * T_DIM + t) * T_DIM;
    const int len = t + 1;

    __shared__ float red[256];

    float mx = -1e30f;
    for (int i = threadIdx.x; i < len; i += 256) mx = fmaxf(mx, row[i]);
    red[threadIdx.x] = mx;
    __syncthreads();
    for (int s = 128; s > 0; s >>= 1) {
        if (threadIdx.x < s) red[threadIdx.x] = fmaxf(red[threadIdx.x], red[threadIdx.x + s]);
        __syncthreads();
    }
    mx = red[0];
    __syncthreads();

    float sum = 0.f;
    for (int i = threadIdx.x; i < len; i += 256) sum += expf(row[i] - mx);
    red[threadIdx.x] = sum;
    __syncthreads();
    for (int s = 128; s > 0; s >>= 1) {
        if (threadIdx.x < s) red[threadIdx.x] += red[threadIdx.x + s];
        __syncthreads();
    }
    const float inv = 1.f / red[0];

    for (int i = threadIdx.x; i < len; i += 256) row[i] = expf(row[i] - mx) * inv;

    const int zend = min(T_DIM, ((t >> 7) + 1) << 7);
    for (int i = len + threadIdx.x; i < zend; i += 256) row[i] = 0.f;
}

// ---------------- launch ------------------------------------------------------
extern "C" void kernel_launch(void* const* d_in, const int* in_sizes, int n_in,
                              void* d_out, int out_size)
{
    const float* hidden    = (const float*)d_in[0];
    const int*   positions = (const int*)d_in[1];
    const float* w_q_a     = (const float*)d_in[2];
    const float* q_a_ln_w  = (const float*)d_in[3];
    const float* w_q_b     = (const float*)d_in[4];
    const float* w_kv_a    = (const float*)d_in[5];
    const float* kv_a_ln_w = (const float*)d_in[6];
    const float* w_kc      = (const float*)d_in[7];
    const float* w_vc      = (const float*)d_in[8];
    const float* w_o       = (const float*)d_in[9];
    float*       out       = (float*)d_out;

    float *qa, *qan, *qproj, *latent, *kin, *cs, *qin, *scores, *ctx, *attn;
    cudaGetSymbolAddress((void**)&qa,     g_qa);
    cudaGetSymbolAddress((void**)&qan,    g_qan);
    cudaGetSymbolAddress((void**)&qproj,  g_qproj);
    cudaGetSymbolAddress((void**)&latent, g_latent);
    cudaGetSymbolAddress((void**)&kin,    g_kin);
    cudaGetSymbolAddress((void**)&cs,     g_cs);
    cudaGetSymbolAddress((void**)&qin,    g_qin);
    cudaGetSymbolAddress((void**)&scores, g_scores);
    cudaGetSymbolAddress((void**)&ctx,    g_ctx);
    cudaGetSymbolAddress((void**)&attn,   g_attn);

    // 1. q_a = hidden @ w_q_a
    hgemm<false, 0><<<dim3(QLR / 128, T_DIM / 128, 1), 256>>>(
        hidden, w_q_a, qa, T_DIM, QLR, HID, HID, QLR, QLR, 0, 0, 0, 1.f);

    // 2. rmsnorm
    rmsnorm_kernel<<<T_DIM, 256>>>(qa, q_a_ln_w, qan, QLR);

    // 3. q = qan @ w_q_b
    hgemm<false, 0><<<dim3(48, T_DIM / 128, 1), 256>>>(
        qan, w_q_b, qproj, T_DIM, H_HEADS * QKD, QLR,
        QLR, H_HEADS * QKD, H_HEADS * QKD, 0, 0, 0, 1.f);

    // 4. latent = hidden @ w_kv_a
    hgemm<false, 0><<<dim3((DQK + 127) / 128, T_DIM / 128, 1), 256>>>(
        hidden, w_kv_a, latent, T_DIM, DQK, HID, HID, DQK, DQK, 0, 0, 0, 1.f);

    // 5. k_input + cos/sin
    build_k_kernel<<<T_DIM, 256>>>(latent, kv_a_ln_w, positions, kin, cs);

    // 6. q_input[h][:, :512] = q_nope_h @ w_kc[h]
    hgemm<false, 0><<<dim3(KVLR / 128, T_DIM / 128, H_HEADS), 256>>>(
        qproj, w_kc, qin, T_DIM, KVLR, NOPE,
        H_HEADS * QKD, KVLR, DQK,
        (long long)QKD, (long long)NOPE * KVLR, (long long)T_DIM * DQK, 1.f);

    // 7. q_input[h][:, 512:576] = rope(q_pe)
    rope_q_kernel<<<dim3(T_DIM, H_HEADS / 8), dim3(32, 8)>>>(qproj, cs, qin);

    // 8. scores = SCALE * q_input @ k_input^T  (causal block-skip)
    hgemm<true, 1><<<dim3(T_DIM / 128, T_DIM / 128, H_HEADS), 256>>>(
        qin, kin, scores, T_DIM, T_DIM, DQK, DQK, DQK, T_DIM,
        (long long)T_DIM * DQK, 0, (long long)T_DIM * T_DIM, ATTN_SCALE);

    // 9. causal softmax
    softmax_kernel<<<dim3(T_DIM, H_HEADS), 256>>>(scores);

    // 10. ctx = probs @ v_input  (K clamped causally)
    hgemm<false, 2><<<dim3(KVLR / 128, T_DIM / 128, H_HEADS), 256>>>(
        scores, kin, ctx, T_DIM, KVLR, T_DIM, T_DIM, DQK, KVLR,
        (long long)T_DIM * T_DIM, 0, (long long)T_DIM * KVLR, 1.f);

    // 11. attn = ctx @ w_vc
    hgemm<false, 0><<<dim3(1, T_DIM / 128, H_HEADS), 256>>>(
        ctx, w_vc, attn, T_DIM, VDIM, KVLR, KVLR, VDIM, H_HEADS * VDIM,
        (long long)T_DIM * KVLR, (long long)KVLR * VDIM, (long long)VDIM, 1.f);

    // 12. out = attn @ w_o
    hgemm<false, 0><<<dim3(HID / 128, T_DIM / 128, 1), 256>>>(
        attn, w_o, out, T_DIM, HID, H_HEADS * VDIM,
        H_HEADS * VDIM, HID, HID, 0, 0, 0, 1.f);
}

// round 6
// speedup vs baseline: 2.4180x; 1.2218x over previous
#include <cuda_runtime.h>
#include <cuda_bf16.h>
#include <math.h>
#include <stdint.h>

// ---------------- problem constants ----------------
#define T_DIM   2048
#define HID     5120
#define QLR     1536
#define KVLR    512
#define NOPE    128
#define ROPE_D  64
#define VDIM    128
#define H_HEADS 32
#define QKD     192
#define DQK     576
#define ATTN_SCALE 0.07216878364870323f
#define RMS_EPS 1e-6f

#define STAGES 3
#define BK 32
#define ROW_U32 20
#define ARR_U32 (128 * ROW_U32)          // 2560
#define STAGE_U32 (4 * ARR_U32)          // 10240
#define SMEM_BYTES (STAGES * STAGE_U32 * 4)   // 122880

// ---------------- fp32 scratch ----------------
__device__ float g_qa    [T_DIM * QLR];
__device__ float g_qproj [T_DIM * H_HEADS * QKD];
__device__ float g_latent[T_DIM * DQK];
__device__ float g_kin   [T_DIM * DQK];
__device__ float g_cs    [T_DIM * ROPE_D];
__device__ float g_qin   [37748736];        // [H][T][576]
__device__ float g_scores[134217728];       // [H][T][T]
__device__ float g_ctx   [33554432];        // [H][T][512]
__device__ float g_attn  [T_DIM * H_HEADS * VDIM];

// ---------------- split-bf16 operand storage (hi/lo) ----------------
#define BDECL(name, n) \
    __device__ __align__(16) __nv_bfloat16 name##_h[n]; \
    __device__ __align__(16) __nv_bfloat16 name##_l[n];

BDECL(b_hid,   10485760)   // hidden [2048][5120]
BDECL(b_wqaT,   7864320)   // [1536][5120]
BDECL(b_qan,    3145728)   // [2048][1536]
BDECL(b_wqbT,   9437184)   // [6144][1536]
BDECL(b_wkvaT,  2949120)   // [576][5120]
BDECL(b_qproj, 12582912)   // [2048][6144]
BDECL(b_wkcT,   2097152)   // [32][512][128]
BDECL(b_qin,   37748736)   // [32][2048][576]
BDECL(b_kin,    1179648)   // [2048][576]
BDECL(b_vT,     1048576)   // [512][2048]
BDECL(b_probs, 134217728)  // [32][2048][2048]
BDECL(b_ctx,   33554432)   // [32][2048][512]
BDECL(b_wvcT,   2097152)   // [32][128][512]
BDECL(b_attn,   8388608)   // [2048][4096]
BDECL(b_woT,   20971520)   // [5120][4096]

// ---------------- helpers ----------------
__device__ __forceinline__ void split1(float x, __nv_bfloat16& h, __nv_bfloat16& l)
{
    h = __float2bfloat16(x);
    l = __float2bfloat16(x - __bfloat162float(h));
}

__device__ __forceinline__ void cp16(void* smem_dst, const void* gsrc)
{
    uint32_t d = (uint32_t)__cvta_generic_to_shared(smem_dst);
    asm volatile("cp.async.ca.shared.global [%0], [%1], 16;" :: "r"(d), "l"(gsrc));
}
#define CP_COMMIT() asm volatile("cp.async.commit_group;")
#define CP_WAIT1()  asm volatile("cp.async.wait_group 1;")

#define MMA16816(c, a, b)                                                      \
    asm volatile("mma.sync.aligned.m16n8k16.row.col.f32.bf16.bf16.f32 "        \
                 "{%0,%1,%2,%3},{%4,%5,%6,%7},{%8,%9},{%0,%1,%2,%3};"          \
                 : "+f"((c)[0]), "+f"((c)[1]), "+f"((c)[2]), "+f"((c)[3])      \
                 : "r"((a)[0]), "r"((a)[1]), "r"((a)[2]), "r"((a)[3]),         \
                   "r"((b)[0]), "r"((b)[1]))

// ---------------- split-bf16 TN GEMM ----------------
// C[M,N] = alpha * A[M,K] @ B^T   (A row-major [M][K], B n-major [N][K], bf16 hi/lo)
// CAUSAL==1: skip tiles strictly above diagonal. CAUSAL==2: Keff = min(K, m0+128).
template <int CAUSAL>
__global__ __launch_bounds__(256)
void gemm_bf16(const __nv_bfloat16* __restrict__ Ah, const __nv_bfloat16* __restrict__ Al,
               const __nv_bfloat16* __restrict__ Bh, const __nv_bfloat16* __restrict__ Bl,
               float* __restrict__ C,
               int M, int N, int K, int lda, int ldb, int ldc,
               long long sA, long long sB, long long sC, float alpha)
{
    const int m0 = blockIdx.y * 128;
    const int n0 = blockIdx.x * 128;
    if (CAUSAL == 1 && n0 > m0 + 127) return;

    Ah += (long long)blockIdx.z * sA;  Al += (long long)blockIdx.z * sA;
    Bh += (long long)blockIdx.z * sB;  Bl += (long long)blockIdx.z * sB;
    C  += (long long)blockIdx.z * sC;

    const int Keff = (CAUSAL == 2) ? min(K, m0 + 128) : K;
    const int nk = Keff / BK;

    extern __shared__ uint32_t smem_u[];

    const int tid  = threadIdx.x;
    const int lane = tid & 31;
    const int warp = tid >> 5;
    const int gid  = lane >> 2;
    const int tig  = lane & 3;
    const int warpM = (warp & 1) * 64;
    const int warpN = (warp >> 1) * 32;

    const int r0 = tid >> 2;             // row (0..63), +64 for second chunk
    const int c0 = tid & 3;              // 16B chunk within 32-k row

    auto load_stage = [&](int slot, int k0) {
        uint32_t* base = smem_u + slot * STAGE_U32;
#pragma unroll
        for (int u = 0; u < 2; u++) {
            int row = r0 + u * 64;
            int kc  = k0 + c0 * 8;
            uint32_t* dA = base + row * ROW_U32 + c0 * 4;
            cp16(dA,             Ah + (long long)(m0 + row) * lda + kc);
            cp16(dA + ARR_U32,   Al + (long long)(m0 + row) * lda + kc);
            int bn = min(n0 + row, N - 1);   // clamp; cols >= N never stored
            uint32_t* dB = base + 2 * ARR_U32 + row * ROW_U32 + c0 * 4;
            cp16(dB,             Bh + (long long)bn * ldb + kc);
            cp16(dB + ARR_U32,   Bl + (long long)bn * ldb + kc);
        }
    };

    float acc[4][4][4];
#pragma unroll
    for (int i = 0; i < 4; i++)
#pragma unroll
        for (int j = 0; j < 4; j++)
#pragma unroll
            for (int c = 0; c < 4; c++) acc[i][j][c] = 0.f;

    for (int s = 0; s < STAGES - 1; s++) {
        if (s < nk) load_stage(s, s * BK);
        CP_COMMIT();
    }

    for (int it = 0; it < nk; it++) {
        CP_WAIT1();
        __syncthreads();

        if (it + STAGES - 1 < nk)
            load_stage((it + STAGES - 1) % STAGES, (it + STAGES - 1) * BK);
        CP_COMMIT();

        const uint32_t* As_h = smem_u + (it % STAGES) * STAGE_U32;
        const uint32_t* As_l = As_h + ARR_U32;
        const uint32_t* Bs_h = As_h + 2 * ARR_U32;
        const uint32_t* Bs_l = As_h + 3 * ARR_U32;

#pragma unroll
        for (int ks = 0; ks < 2; ks++) {
            const int cb = ks * 8;
            uint32_t af[4][4], bh4[4][2], bl4[4][2];
#pragma unroll
            for (int i = 0; i < 4; i++) {
                int m = warpM + i * 16 + gid;
                af[i][0] = As_h[m * ROW_U32 + cb + tig];
                af[i][1] = As_h[(m + 8) * ROW_U32 + cb + tig];
                af[i][2] = As_h[m * ROW_U32 + cb + tig + 4];
                af[i][3] = As_h[(m + 8) * ROW_U32 + cb + tig + 4];
            }
#pragma unroll
            for (int j = 0; j < 4; j++) {
                int n = warpN + j * 8 + gid;
                bh4[j][0] = Bs_h[n * ROW_U32 + cb + tig];
                bh4[j][1] = Bs_h[n * ROW_U32 + cb + tig + 4];
                bl4[j][0] = Bs_l[n * ROW_U32 + cb + tig];
                bl4[j][1] = Bs_l[n * ROW_U32 + cb + tig + 4];
            }
#pragma unroll
            for (int i = 0; i < 4; i++)
#pragma unroll
                for (int j = 0; j < 4; j++) {
                    MMA16816(acc[i][j], af[i], bh4[j]);   // hi*hi
                    MMA16816(acc[i][j], af[i], bl4[j]);   // hi*lo
                }
#pragma unroll
            for (int i = 0; i < 4; i++) {
                int m = warpM + i * 16 + gid;
                af[i][0] = As_l[m * ROW_U32 + cb + tig];
                af[i][1] = As_l[(m + 8) * ROW_U32 + cb + tig];
                af[i][2] = As_l[m * ROW_U32 + cb + tig + 4];
                af[i][3] = As_l[(m + 8) * ROW_U32 + cb + tig + 4];
            }
#pragma unroll
            for (int i = 0; i < 4; i++)
#pragma unroll
                for (int j = 0; j < 4; j++)
                    MMA16816(acc[i][j], af[i], bh4[j]);   // lo*hi
        }
        __syncthreads();
    }

#pragma unroll
    for (int i = 0; i < 4; i++) {
#pragma unroll
        for (int j = 0; j < 4; j++) {
            int r = m0 + warpM + i * 16 + gid;
            int cn = n0 + warpN + j * 8 + 2 * tig;
            if (cn < N) {
                float2 v0 = make_float2(acc[i][j][0] * alpha, acc[i][j][1] * alpha);
                float2 v1 = make_float2(acc[i][j][2] * alpha, acc[i][j][3] * alpha);
                *(float2*)(C + (long long)r * ldc + cn)       = v0;
                *(float2*)(C + (long long)(r + 8) * ldc + cn) = v1;
            }
        }
    }
}

// ---------------- convert: fp32 row-major -> split bf16 ----------------------
__global__ void convert_row_split(const float* __restrict__ in,
                                  __nv_bfloat16* __restrict__ oh,
                                  __nv_bfloat16* __restrict__ ol)
{
    long long idx = ((long long)blockIdx.x * 256 + threadIdx.x) * 4;
    float4 f = *(const float4*)(in + idx);
    __nv_bfloat16 h[4], l[4];
    split1(f.x, h[0], l[0]); split1(f.y, h[1], l[1]);
    split1(f.z, h[2], l[2]); split1(f.w, h[3], l[3]);
    *(uint2*)(oh + idx) = *(uint2*)h;
    *(uint2*)(ol + idx) = *(uint2*)l;
}

// ---------------- transpose: fp32 [R][C] -> split bf16 [C][R] ----------------
__global__ void transpose_split(const float* __restrict__ in, int ldin,
                                int R, int Ccols,
                                __nv_bfloat16* __restrict__ oh,
                                __nv_bfloat16* __restrict__ ol,
                                long long sIn, long long sOut)
{
    __shared__ float tile[32][33];
    in += (long long)blockIdx.z * sIn;
    oh += (long long)blockIdx.z * sOut;
    ol += (long long)blockIdx.z * sOut;
    const int cb = blockIdx.x * 32;
    const int rb = blockIdx.y * 32;
#pragma unroll
    for (int i = 0; i < 4; i++) {
        int r = rb + threadIdx.y + i * 8;
        int c = cb + threadIdx.x;
        tile[threadIdx.y + i * 8][threadIdx.x] =
            (r < R && c < Ccols) ? in[(long long)r * ldin + c] : 0.f;
    }
    __syncthreads();
#pragma unroll
    for (int i = 0; i < 4; i++) {
        int c = cb + threadIdx.y + i * 8;
        int r = rb + threadIdx.x;
        if (c < Ccols && r < R) {
            __nv_bfloat16 h, l;
            split1(tile[threadIdx.x][threadIdx.y + i * 8], h, l);
            oh[(long long)c * R + r] = h;
            ol[(long long)c * R + r] = l;
        }
    }
}

// ---------------- RMSNorm with fused split output ---------------------------
__global__ void rmsnorm_split(const float* __restrict__ x,
                              const float* __restrict__ w,
                              __nv_bfloat16* __restrict__ yh,
                              __nv_bfloat16* __restrict__ yl, int D)
{
    const int row = blockIdx.x;
    const float* xr = x + (long long)row * D;

    float ss = 0.f;
    for (int i = threadIdx.x; i < D; i += 256) { float v = xr[i]; ss += v * v; }
    __shared__ float red[256];
    red[threadIdx.x] = ss;
    __syncthreads();
    for (int s = 128; s > 0; s >>= 1) {
        if (threadIdx.x < s) red[threadIdx.x] += red[threadIdx.x + s];
        __syncthreads();
    }
    const float r = rsqrtf(red[0] / (float)D + RMS_EPS);
    for (int i = threadIdx.x; i < D; i += 256) {
        __nv_bfloat16 h, l;
        split1(xr[i] * r * w[i], h, l);
        yh[(long long)row * D + i] = h;
        yl[(long long)row * D + i] = l;
    }
}

// ---------------- build k_input + cos/sin ------------------------------------
__global__ void build_k_kernel(const float* __restrict__ latent,
                               const float* __restrict__ w,
                               const int* __restrict__ pos32,
                               float* __restrict__ kin,
                               float* __restrict__ cs)
{
    const int t = blockIdx.x;
    const float* lr = latent + (long long)t * DQK;
    float* kr       = kin    + (long long)t * DQK;

    float ss = 0.f;
    for (int i = threadIdx.x; i < KVLR; i += 256) { float v = lr[i]; ss += v * v; }
    __shared__ float red[256];
    red[threadIdx.x] = ss;
    __syncthreads();
    for (int s = 128; s > 0; s >>= 1) {
        if (threadIdx.x < s) red[threadIdx.x] += red[threadIdx.x + s];
        __syncthreads();
    }
    const float r = rsqrtf(red[0] / (float)KVLR + RMS_EPS);
    for (int i = threadIdx.x; i < KVLR; i += 256) kr[i] = lr[i] * r * w[i];

    if (threadIdx.x < 32) {
        const int j = threadIdx.x;
        const bool is64 = (pos32[1] == 0);
        const long long p = is64 ? ((const long long*)pos32)[t]
                                 : (long long)pos32[t];
        const double inv = pow(10000.0, -(double)(2 * j) / (double)ROPE_D);
        const double ang = (double)p * inv;
        const float c = (float)cos(ang);
        const float s = (float)sin(ang);
        cs[t * ROPE_D + j]      = c;
        cs[t * ROPE_D + 32 + j] = s;
        const float x1 = lr[KVLR + 2 * j];
        const float x2 = lr[KVLR + 2 * j + 1];
        kr[KVLR + 2 * j]     = x1 * c - x2 * s;
        kr[KVLR + 2 * j + 1] = x2 * c + x1 * s;
    }
}

// ---------------- rope q_pe -> g_qin[.., 512:576] ----------------------------
__global__ void rope_q_kernel(const float* __restrict__ q,
                              const float* __restrict__ cs,
                              float* __restrict__ qin)
{
    const int t = blockIdx.x;
    const int h = blockIdx.y * blockDim.y + threadIdx.y;
    const int j = threadIdx.x;

    const float c = cs[t * ROPE_D + j];
    const float s = cs[t * ROPE_D + 32 + j];
    const float* qr = q + (long long)t * (H_HEADS * QKD) + h * QKD + NOPE;
    const float x1 = qr[2 * j];
    const float x2 = qr[2 * j + 1];
    float* o = qin + ((long long)h * T_DIM + t) * DQK + KVLR;
    o[2 * j]     = x1 * c - x2 * s;
    o[2 * j + 1] = x2 * c + x1 * s;
}

// ---------------- causal softmax with fused split-bf16 output ----------------
__global__ void softmax_split(const float* __restrict__ scores,
                              __nv_bfloat16* __restrict__ ph,
                              __nv_bfloat16* __restrict__ pl)
{
    const int t = blockIdx.x;
    const int h = blockIdx.y;
    const long long off = ((long long)h * T_DIM + t) * T_DIM;
    const float* row = scores + off;
    const int len = t + 1;

    __shared__ float red[256];

    float mx = -1e30f;
    for (int i = threadIdx.x; i < len; i += 256) mx = fmaxf(mx, row[i]);
    red[threadIdx.x] = mx;
    __syncthreads();
    for (int s = 128; s > 0; s >>= 1) {
        if (threadIdx.x < s) red[threadIdx.x] = fmaxf(red[threadIdx.x], red[threadIdx.x + s]);
        __syncthreads();
    }
    mx = red[0];
    __syncthreads();

    float sum = 0.f;
    for (int i = threadIdx.x; i < len; i += 256) sum += expf(row[i] - mx);
    red[threadIdx.x] = sum;
    __syncthreads();
    for (int s = 128; s > 0; s >>= 1) {
        if (threadIdx.x < s) red[threadIdx.x] += red[threadIdx.x + s];
        __syncthreads();
    }
    const float inv = 1.f / red[0];

    for (int i = threadIdx.x; i < len; i += 256) {
        __nv_bfloat16 hh, ll;
        split1(expf(row[i] - mx) * inv, hh, ll);
        ph[off + i] = hh;
        pl[off + i] = ll;
    }
    const int zend = min(T_DIM, ((t >> 7) + 1) << 7);
    const __nv_bfloat16 z = __float2bfloat16(0.f);
    for (int i = len + threadIdx.x; i < zend; i += 256) { ph[off + i] = z; pl[off + i] = z; }
}

// ---------------- launch ------------------------------------------------------
#define SYM(p, s) cudaGetSymbolAddress((void**)&p, s)

extern "C" void kernel_launch(void* const* d_in, const int* in_sizes, int n_in,
                              void* d_out, int out_size)
{
    const float* hidden    = (const float*)d_in[0];
    const int*   positions = (const int*)d_in[1];
    const float* w_q_a     = (const float*)d_in[2];
    const float* q_a_ln_w  = (const float*)d_in[3];
    const float* w_q_b     = (const float*)d_in[4];
    const float* w_kv_a    = (const float*)d_in[5];
    const float* kv_a_ln_w = (const float*)d_in[6];
    const float* w_kc      = (const float*)d_in[7];
    const float* w_vc      = (const float*)d_in[8];
    const float* w_o       = (const float*)d_in[9];
    float*       out       = (float*)d_out;

    float *qa, *qproj, *latent, *kin, *cs, *qin, *scores, *ctx, *attn;
    SYM(qa, g_qa); SYM(qproj, g_qproj); SYM(latent, g_latent); SYM(kin, g_kin);
    SYM(cs, g_cs); SYM(qin, g_qin); SYM(scores, g_scores); SYM(ctx, g_ctx); SYM(attn, g_attn);

    __nv_bfloat16 *hid_h,*hid_l, *wqaT_h,*wqaT_l, *qan_h,*qan_l, *wqbT_h,*wqbT_l,
                  *wkvaT_h,*wkvaT_l, *qpr_h,*qpr_l, *wkcT_h,*wkcT_l, *qin_h,*qin_l,
                  *kin_h,*kin_l, *vT_h,*vT_l, *pr_h,*pr_l, *ctx_h,*ctx_l,
                  *wvcT_h,*wvcT_l, *att_h,*att_l, *woT_h,*woT_l;
    SYM(hid_h,b_hid_h);   SYM(hid_l,b_hid_l);
    SYM(wqaT_h,b_wqaT_h); SYM(wqaT_l,b_wqaT_l);
    SYM(qan_h,b_qan_h);   SYM(qan_l,b_qan_l);
    SYM(wqbT_h,b_wqbT_h); SYM(wqbT_l,b_wqbT_l);
    SYM(wkvaT_h,b_wkvaT_h); SYM(wkvaT_l,b_wkvaT_l);
    SYM(qpr_h,b_qproj_h); SYM(qpr_l,b_qproj_l);
    SYM(wkcT_h,b_wkcT_h); SYM(wkcT_l,b_wkcT_l);
    SYM(qin_h,b_qin_h);   SYM(qin_l,b_qin_l);
    SYM(kin_h,b_kin_h);   SYM(kin_l,b_kin_l);
    SYM(vT_h,b_vT_h);     SYM(vT_l,b_vT_l);
    SYM(pr_h,b_probs_h);  SYM(pr_l,b_probs_l);
    SYM(ctx_h,b_ctx_h);   SYM(ctx_l,b_ctx_l);
    SYM(wvcT_h,b_wvcT_h); SYM(wvcT_l,b_wvcT_l);
    SYM(att_h,b_attn_h);  SYM(att_l,b_attn_l);
    SYM(woT_h,b_woT_h);   SYM(woT_l,b_woT_l);

    cudaFuncSetAttribute(gemm_bf16<0>, cudaFuncAttributeMaxDynamicSharedMemorySize, SMEM_BYTES);
    cudaFuncSetAttribute(gemm_bf16<1>, cudaFuncAttributeMaxDynamicSharedMemorySize, SMEM_BYTES);
    cudaFuncSetAttribute(gemm_bf16<2>, cudaFuncAttributeMaxDynamicSharedMemorySize, SMEM_BYTES);

    dim3 tb(32, 8);

    // ---- operand conversion (weights + hidden) ----
    convert_row_split<<<10240, 256>>>(hidden, hid_h, hid_l);                          // 2048x5120
    transpose_split<<<dim3(48, 160, 1), tb>>>(w_q_a, QLR, HID, QLR, wqaT_h, wqaT_l, 0, 0);
    transpose_split<<<dim3(192, 48, 1), tb>>>(w_q_b, H_HEADS*QKD, QLR, H_HEADS*QKD, wqbT_h, wqbT_l, 0, 0);
    transpose_split<<<dim3(18, 160, 1), tb>>>(w_kv_a, DQK, HID, DQK, wkvaT_h, wkvaT_l, 0, 0);
    transpose_split<<<dim3(16, 4, H_HEADS), tb>>>(w_kc, KVLR, NOPE, KVLR, wkcT_h, wkcT_l,
                                                  (long long)NOPE*KVLR, (long long)KVLR*NOPE);
    transpose_split<<<dim3(4, 16, H_HEADS), tb>>>(w_vc, VDIM, KVLR, VDIM, wvcT_h, wvcT_l,
                                                  (long long)KVLR*VDIM, (long long)VDIM*KVLR);
    transpose_split<<<dim3(160, 128, 1), tb>>>(w_o, HID, H_HEADS*VDIM, HID, woT_h, woT_l, 0, 0);

    // 1. q_a = hidden @ w_q_a
    gemm_bf16<0><<<dim3(12, 16, 1), 256, SMEM_BYTES>>>(
        hid_h, hid_l, wqaT_h, wqaT_l, qa, T_DIM, QLR, HID, HID, HID, QLR, 0, 0, 0, 1.f);
    // 2. rmsnorm -> split bf16
    rmsnorm_split<<<T_DIM, 256>>>(qa, q_a_ln_w, qan_h, qan_l, QLR);
    // 3. q = qan @ w_q_b
    gemm_bf16<0><<<dim3(48, 16, 1), 256, SMEM_BYTES>>>(
        qan_h, qan_l, wqbT_h, wqbT_l, qproj, T_DIM, H_HEADS*QKD, QLR, QLR, QLR,
        H_HEADS*QKD, 0, 0, 0, 1.f);
    // 4. latent = hidden @ w_kv_a
    gemm_bf16<0><<<dim3(5, 16, 1), 256, SMEM_BYTES>>>(
        hid_h, hid_l, wkvaT_h, wkvaT_l, latent, T_DIM, DQK, HID, HID, HID, DQK, 0, 0, 0, 1.f);
    // 5. k_input + cos/sin
    build_k_kernel<<<T_DIM, 256>>>(latent, kv_a_ln_w, positions, kin, cs);
    convert_row_split<<<1152, 256>>>(kin, kin_h, kin_l);                              // 2048x576
    transpose_split<<<dim3(16, 64, 1), tb>>>(kin, DQK, T_DIM, KVLR, vT_h, vT_l, 0, 0); // vT[512][2048]
    // 6. q_nope projection
    convert_row_split<<<12288, 256>>>(qproj, qpr_h, qpr_l);                           // 2048x6144
    gemm_bf16<0><<<dim3(4, 16, H_HEADS), 256, SMEM_BYTES>>>(
        qpr_h, qpr_l, wkcT_h, wkcT_l, qin, T_DIM, KVLR, NOPE,
        H_HEADS*QKD, NOPE, DQK, (long long)QKD, (long long)KVLR*NOPE, (long long)T_DIM*DQK, 1.f);
    // 7. rope q_pe, then convert q_input
    rope_q_kernel<<<dim3(T_DIM, H_HEADS/8), dim3(32, 8)>>>(qproj, cs, qin);
    convert_row_split<<<36864, 256>>>(qin, qin_h, qin_l);                             // 32x2048x576
    // 8. scores = SCALE * q_input @ k_input^T (causal skip)
    gemm_bf16<1><<<dim3(16, 16, H_HEADS), 256, SMEM_BYTES>>>(
        qin_h, qin_l, kin_h, kin_l, scores, T_DIM, T_DIM, DQK, DQK, DQK, T_DIM,
        (long long)T_DIM*DQK, 0, (long long)T_DIM*T_DIM, ATTN_SCALE);
    // 9. softmax -> split bf16 probs
    softmax_split<<<dim3(T_DIM, H_HEADS), 256>>>(scores, pr_h, pr_l);
    // 10. ctx = probs @ v_input (K causally clamped)
    gemm_bf16<2><<<dim3(4, 16, H_HEADS), 256, SMEM_BYTES>>>(
        pr_h, pr_l, vT_h, vT_l, ctx, T_DIM, KVLR, T_DIM, T_DIM, T_DIM, KVLR,
        (long long)T_DIM*T_DIM, 0, (long long)T_DIM*KVLR, 1.f);
    // 11. attn = ctx @ w_vc
    convert_row_split<<<32768, 256>>>(ctx, ctx_h, ctx_l);                             // 32x2048x512
    gemm_bf16<0><<<dim3(1, 16, H_HEADS), 256, SMEM_BYTES>>>(
        ctx_h, ctx_l, wvcT_h, wvcT_l, attn, T_DIM, VDIM, KVLR, KVLR, KVLR,
        H_HEADS*VDIM, (long long)T_DIM*KVLR, (long long)VDIM*KVLR, (long long)VDIM, 1.f);
    // 12. out = attn @ w_o
    convert_row_split<<<8192, 256>>>(attn, att_h, att_l);                             // 2048x4096
    gemm_bf16<0><<<dim3(40, 16, 1), 256, SMEM_BYTES>>>(
        att_h, att_l, woT_h, woT_l, out, T_DIM, HID, H_HEADS*VDIM,
        H_HEADS*VDIM, H_HEADS*VDIM, HID, 0, 0, 0, 1.f);
}